// round 8
// baseline (speedup 1.0000x reference)
#include <cuda_runtime.h>
#include <cstdint>

#define K_DIM 4096
#define BM 128
#define BN 128
#define BKB 32              // K bytes per pipeline stage
#define KCH (K_DIM / BKB)   // 128 chunks
#define SROW 48             // padded smem row stride (bank = r*12+c -> conflict-free)
#define STG_BYTES (BM * SROW)

#define X_ELEMS (33554432LL)   // 2*4096*4096
#define W_ELEMS (45088768LL)   // 11008*4096

// Scratch int8 buffers (device globals: allowed, no runtime allocation)
__device__ int8_t g_x8[X_ELEMS];
__device__ int8_t g_w8[W_ELEMS];

// ---------------------------------------------------------------------------
// Dtype-agnostic 32-bit -> int8 conversion. The harness canonicalizes int8
// tensors to a 32-bit dtype (int32 or float32). Per 32-bit word:
//   - if the word interpreted as int32 is in [-128, 127] -> it IS the value
//     (int32 storage; float32 bit patterns of values in [-127,126]\{0} are
//      huge as ints, so no collision)
//   - else reinterpret as float32 and round (float32 storage)
// ---------------------------------------------------------------------------
__global__ void cvt32_to_i8(const uint32_t* __restrict__ src, int8_t* __restrict__ dst, int n4) {
    int i = blockIdx.x * blockDim.x + threadIdx.x;
    if (i >= n4) return;
    uint4 v = reinterpret_cast<const uint4*>(src)[i];
    uint32_t ws[4] = {v.x, v.y, v.z, v.w};
    int8_t r[4];
    #pragma unroll
    for (int q = 0; q < 4; q++) {
        int iv = (int)ws[q];
        if (iv < -128 || iv > 127)
            iv = (int)rintf(__int_as_float((int)ws[q]));
        r[q] = (int8_t)iv;
    }
    uint32_t packed = (uint8_t)r[0] | ((uint8_t)r[1] << 8) | ((uint8_t)r[2] << 16) | ((uint8_t)r[3] << 24);
    reinterpret_cast<uint32_t*>(dst)[i] = packed;
}

__device__ __forceinline__ float silu(float y) {
    return y * (1.0f / (1.0f + __expf(-y)));
}

// int8 GEMM + SiLU epilogue (exact int32 accumulate).
//   out[m, n] = SiLU(alpha * sum_k x[m,k]*w[n,k] + bias[n])
// mma.sync m16n8k32 row.col: A = x tile (row-major m x k), B = weight tile
// (col-major k x n == weight's natural [n][k] layout).
__global__ void __launch_bounds__(256, 2) w8a8_mma_silu(
    const int8_t* __restrict__ x, const int8_t* __restrict__ wgt,
    const float* __restrict__ bias, const float* __restrict__ alpha_p,
    float* __restrict__ out, int Nout)
{
    __shared__ uint8_t As[2][STG_BYTES];
    __shared__ uint8_t Bs[2][STG_BYTES];

    const int tid = threadIdx.x;
    const int l   = tid & 31;
    const int w   = tid >> 5;
    const int wm  = w >> 2;      // 0..1  (m warp coord, 64 rows each)
    const int wn  = w & 3;       // 0..3  (n warp coord, 32 cols each)

    // global->smem copy mapping: 256 threads cover 128 rows x 2 16B segments
    const int row = tid >> 1;
    const int seg = (tid & 1) * 16;

    const int8_t* xsrc = x   + (size_t)(blockIdx.y * BM + row) * K_DIM + seg;
    const int8_t* wsrc = wgt + (size_t)(blockIdx.x * BN + row) * K_DIM + seg;

    uint32_t a_dst[2], b_dst[2];
    #pragma unroll
    for (int s = 0; s < 2; s++) {
        a_dst[s] = (uint32_t)__cvta_generic_to_shared(&As[s][row * SROW + seg]);
        b_dst[s] = (uint32_t)__cvta_generic_to_shared(&Bs[s][row * SROW + seg]);
    }

    // prologue: fill stage 0
    asm volatile("cp.async.cg.shared.global [%0], [%1], 16;" :: "r"(a_dst[0]), "l"(xsrc));
    asm volatile("cp.async.cg.shared.global [%0], [%1], 16;" :: "r"(b_dst[0]), "l"(wsrc));
    asm volatile("cp.async.commit_group;");

    int acc[4][4][4];
    #pragma unroll
    for (int i = 0; i < 4; i++)
        #pragma unroll
        for (int j = 0; j < 4; j++)
            #pragma unroll
            for (int r = 0; r < 4; r++) acc[i][j][r] = 0;

    // per-lane fragment smem offsets (PTX m16n8k32 s8 layouts):
    //   A a0: row = base + l>>2, k-bytes (l&3)*4; a1: row+8; a2/a3: +16 in k
    //   B b0: col = base + l>>2, k-bytes (l&3)*4; b1: +16 in k
    const int fr = l >> 2;          // 0..7
    const int fc = (l & 3) * 4;     // 0,4,8,12

    for (int kk = 0; kk < KCH; kk++) {
        const int cur = kk & 1;
        if (kk + 1 < KCH) {
            const int nxt = cur ^ 1;
            asm volatile("cp.async.cg.shared.global [%0], [%1], 16;"
                         :: "r"(a_dst[nxt]), "l"(xsrc + (kk + 1) * BKB));
            asm volatile("cp.async.cg.shared.global [%0], [%1], 16;"
                         :: "r"(b_dst[nxt]), "l"(wsrc + (kk + 1) * BKB));
            asm volatile("cp.async.commit_group;");
            asm volatile("cp.async.wait_group 1;");
        } else {
            asm volatile("cp.async.wait_group 0;");
        }
        __syncthreads();

        uint32_t a[4][4];
        #pragma unroll
        for (int i = 0; i < 4; i++) {
            const int r0 = (wm * 64 + i * 16 + fr) * SROW + fc;
            a[i][0] = *(const uint32_t*)&As[cur][r0];
            a[i][1] = *(const uint32_t*)&As[cur][r0 + 8 * SROW];
            a[i][2] = *(const uint32_t*)&As[cur][r0 + 16];
            a[i][3] = *(const uint32_t*)&As[cur][r0 + 8 * SROW + 16];
        }
        uint32_t b[4][2];
        #pragma unroll
        for (int j = 0; j < 4; j++) {
            const int c0 = (wn * 32 + j * 8 + fr) * SROW + fc;
            b[j][0] = *(const uint32_t*)&Bs[cur][c0];
            b[j][1] = *(const uint32_t*)&Bs[cur][c0 + 16];
        }

        #pragma unroll
        for (int i = 0; i < 4; i++)
            #pragma unroll
            for (int j = 0; j < 4; j++)
                asm volatile(
                    "mma.sync.aligned.m16n8k32.row.col.s32.s8.s8.s32 "
                    "{%0,%1,%2,%3}, {%4,%5,%6,%7}, {%8,%9}, {%0,%1,%2,%3};"
                    : "+r"(acc[i][j][0]), "+r"(acc[i][j][1]),
                      "+r"(acc[i][j][2]), "+r"(acc[i][j][3])
                    : "r"(a[i][0]), "r"(a[i][1]), "r"(a[i][2]), "r"(a[i][3]),
                      "r"(b[j][0]), "r"(b[j][1]));

        __syncthreads();
    }

    // epilogue: y = SiLU(alpha*acc + bias[n]); D frag rows l>>2 / +8, cols (l&3)*2 +0/1
    const float alpha = *alpha_p;
    #pragma unroll
    for (int i = 0; i < 4; i++) {
        #pragma unroll
        for (int h = 0; h < 2; h++) {
            const int m = blockIdx.y * BM + wm * 64 + i * 16 + fr + h * 8;
            float* orow = out + (size_t)m * Nout;
            #pragma unroll
            for (int j = 0; j < 4; j++) {
                const int n = blockIdx.x * BN + wn * 32 + j * 8 + (l & 3) * 2;
                const float b0 = bias[n], b1 = bias[n + 1];
                float y0 = fmaf(alpha, (float)acc[i][j][h * 2],     b0);
                float y1 = fmaf(alpha, (float)acc[i][j][h * 2 + 1], b1);
                float2 v = make_float2(silu(y0), silu(y1));
                *(float2*)(orow + n) = v;
            }
        }
    }
}

extern "C" void kernel_launch(void* const* d_in, const int* in_sizes, int n_in,
                              void* d_out, int out_size) {
    // Order-independent binding by element count (pairwise distinct):
    //   x: 33,554,432   weight: 45,088,768 (largest)   bias: 11,008   alpha: 1
    const void* xr = nullptr; const void* wr = nullptr;
    const float* bias = nullptr; const float* alpha = nullptr;
    long long xsz = 0, bsz = 0;

    int big0 = -1, big1 = -1;
    for (int i = 0; i < n_in; i++) {
        long long s = in_sizes[i];
        if (s == 1)            alpha = (const float*)d_in[i];
        else if (s > 100000) { if (big0 < 0) big0 = i; else big1 = i; }
        else                 { bias = (const float*)d_in[i]; bsz = s; }
    }
    long long wsz;
    if ((long long)in_sizes[big0] >= (long long)in_sizes[big1]) {
        wr = d_in[big0]; wsz = in_sizes[big0];
        xr = d_in[big1]; xsz = in_sizes[big1];
    } else {
        wr = d_in[big1]; wsz = in_sizes[big1];
        xr = d_in[big0]; xsz = in_sizes[big0];
    }

    float* out = (float*)d_out;
    const int Nout  = (int)bsz;             // 11008
    const int Mrows = (int)(xsz / K_DIM);   // 8192

    // Resolve scratch buffer addresses (query only; no allocation)
    void* xp; void* wp;
    cudaGetSymbolAddress(&xp, g_x8);
    cudaGetSymbolAddress(&wp, g_w8);
    int8_t* x8 = (int8_t*)xp;
    int8_t* w8 = (int8_t*)wp;

    // Pre-pass: canonicalize 32-bit-stored int8 tensors into packed int8
    {
        int n4x = (int)(xsz / 4);
        int n4w = (int)(wsz / 4);
        cvt32_to_i8<<<(n4x + 255) / 256, 256>>>((const uint32_t*)xr, x8, n4x);
        cvt32_to_i8<<<(n4w + 255) / 256, 256>>>((const uint32_t*)wr, w8, n4w);
    }

    // n-tiles fast: weight panel (43 MB int8) stays L2-resident across m-waves
    dim3 grid(Nout / BN, Mrows / BM);
    w8a8_mma_silu<<<grid, 256>>>(x8, w8, bias, alpha, out, Nout);
}

// round 15
// speedup vs baseline: 5.2183x; 5.2183x over previous
#include <cuda_runtime.h>
#include <cuda_fp16.h>
#include <cstdint>

#define K_DIM 4096
#define KIT   64                // K chunks of 64 fp16 elems (128 B/row)
#define NSTAGE 3
#define SM_STAGE 32768          // A tile 16KB + B tile 16KB per stage
#define SM_TILES 1024
#define SMEM_DYN (SM_TILES + NSTAGE * SM_STAGE)   // 99328 B

#define X_ELEMS (33554432LL)    // 2*4096*4096
#define W_ELEMS (45088768LL)    // 11008*4096

// Scratch buffers (device globals: legal, no runtime allocation)
__device__ int8_t g_x8[X_ELEMS];
__device__ int8_t g_w8[W_ELEMS];
__device__ __half g_x16[X_ELEMS];
__device__ __half g_w16[W_ELEMS];

// ---------------------------------------------------------------------------
// 32-bit -> {int8, fp16} canonicalization (int8 decode PROVEN in R8).
// Per word: if the int32 value is in [-128,127] it IS the value; else
// reinterpret as float32 and round.
// ---------------------------------------------------------------------------
__global__ void cvt32(const uint32_t* __restrict__ src, int8_t* __restrict__ d8,
                      __half* __restrict__ d16, int n4) {
    int i = blockIdx.x * blockDim.x + threadIdx.x;
    if (i >= n4) return;
    uint4 v = reinterpret_cast<const uint4*>(src)[i];
    uint32_t ws[4] = {v.x, v.y, v.z, v.w};
    int iv[4];
    #pragma unroll
    for (int q = 0; q < 4; q++) {
        iv[q] = (int)ws[q];
        if (iv[q] < -128 || iv[q] > 127)
            iv[q] = (int)rintf(__int_as_float((int)ws[q]));
    }
    uint32_t packed = (uint8_t)(int8_t)iv[0] | ((uint8_t)(int8_t)iv[1] << 8) |
                      ((uint8_t)(int8_t)iv[2] << 16) | ((uint8_t)(int8_t)iv[3] << 24);
    reinterpret_cast<uint32_t*>(d8)[i] = packed;

    __half2 h0 = __halves2half2(__float2half_rn((float)iv[0]), __float2half_rn((float)iv[1]));
    __half2 h1 = __halves2half2(__float2half_rn((float)iv[2]), __float2half_rn((float)iv[3]));
    uint2 o;
    o.x = *reinterpret_cast<uint32_t*>(&h0);
    o.y = *reinterpret_cast<uint32_t*>(&h1);
    reinterpret_cast<uint2*>(d16)[i] = o;
}

__device__ __forceinline__ float silu(float y) {
    return y * (1.0f / (1.0f + __expf(-y)));
}

// ---------------------------------------------------------------------------
// Arch gating: tcgen05 only exists in 'a'/family-specific passes; the plain
// compute_103 pass compiles the PROVEN R7 mma.sync int8 body instead.
// ---------------------------------------------------------------------------
#if defined(__CUDA_ARCH__) && \
    (defined(__CUDA_ARCH_FEAT_SM103_ALL) || defined(__CUDA_ARCH_FEAT_SM100_ALL) || \
     defined(__CUDA_ARCH_FEAT_SM101_ALL) || defined(__CUDA_ARCH_SPECIFIC__) || \
     defined(__CUDA_ARCH_FAMILY_SPECIFIC__))
#  define USE_TCGEN05 1
#else
#  define USE_TCGEN05 0
#endif

#if USE_TCGEN05
// idesc kind::f16: dtype=F32(1)<<4, atype=f16(0), btype=f16(0),
// N=128 -> 16<<17, M=128 -> 8<<24   (family verified by test_mma 0x8080490)
#define IDESC_F16 ((1u << 4) | (16u << 17) | (8u << 24))   // 0x8200010

static __device__ __forceinline__ uint64_t make_desc(uint32_t addr) {
    const uint64_t base =   // SW128(2), version=1, SBO=64, LBO=1 (K-major)
        (uint64_t(2) << 61) | (uint64_t(1) << 46) | (uint64_t(64) << 32) | (uint64_t(1) << 16);
    return base | ((uint64_t)(addr >> 4) & 0x3FFF);
}
static __device__ __forceinline__ uint32_t cvta_smem(const void* p) {
    uint32_t a;
    asm("{ .reg .u64 t; cvta.to.shared.u64 t, %1; cvt.u32.u64 %0, t; }" : "=r"(a) : "l"(p));
    return a;
}
static __device__ __forceinline__ uint32_t elect_one() {
    uint32_t p;
    asm volatile("{ .reg .pred P; elect.sync _|P, 0xFFFFFFFF; selp.b32 %0, 1, 0, P; }" : "=r"(p));
    return p;
}
static __device__ __forceinline__ void mbar_wait(uint32_t mb, uint32_t parity) {
    asm volatile(
        "{ .reg .pred P;\n"
        "LW%=:\n"
        " mbarrier.try_wait.parity.acquire.cta.shared::cta.b64 P, [%0], %1, 0x989680;\n"
        " @P bra.uni LD%=;\n"
        " bra.uni LW%=;\n"
        "LD%=: }\n"
        :: "r"(mb), "r"(parity) : "memory");
}
static __device__ __forceinline__ void mma_f16_ss(uint32_t d, uint64_t ad, uint64_t bd, uint32_t en) {
    asm volatile(
        "{ .reg .pred p; setp.ne.u32 p, %4, 0;\n"
        "  tcgen05.mma.cta_group::1.kind::f16 [%0], %1, %2, %3, {%5,%5,%5,%5}, p; }\n"
        :: "r"(d), "l"(ad), "l"(bd), "r"(IDESC_F16), "r"(en), "r"(0u) : "memory");
}
static __device__ __forceinline__ void ldtm_x32(uint32_t* r, uint32_t taddr) {
    asm volatile(
        "tcgen05.ld.sync.aligned.32x32b.x32.b32 "
        "{%0,%1,%2,%3,%4,%5,%6,%7,%8,%9,%10,%11,%12,%13,%14,%15,"
        "%16,%17,%18,%19,%20,%21,%22,%23,%24,%25,%26,%27,%28,%29,%30,%31}, [%32];"
        : "=r"(r[0]), "=r"(r[1]), "=r"(r[2]), "=r"(r[3]),
          "=r"(r[4]), "=r"(r[5]), "=r"(r[6]), "=r"(r[7]),
          "=r"(r[8]), "=r"(r[9]), "=r"(r[10]), "=r"(r[11]),
          "=r"(r[12]), "=r"(r[13]), "=r"(r[14]), "=r"(r[15]),
          "=r"(r[16]), "=r"(r[17]), "=r"(r[18]), "=r"(r[19]),
          "=r"(r[20]), "=r"(r[21]), "=r"(r[22]), "=r"(r[23]),
          "=r"(r[24]), "=r"(r[25]), "=r"(r[26]), "=r"(r[27]),
          "=r"(r[28]), "=r"(r[29]), "=r"(r[30]), "=r"(r[31])
        : "r"(taddr));
}
#define CP16(dst, src) \
    asm volatile("cp.async.cg.shared.global [%0], [%1], 16;" :: "r"(dst), "l"(src))
#endif  // USE_TCGEN05

// ===========================================================================
// out[m, n] = SiLU(alpha * sum_k x[m,k]*w[n,k] + bias[n])
// tcgen05 path: fp16 operands (exact for int8 data), fp32 accumulate.
// A = weight tile (M dim = out features -> TMEM lane = n, coalesced epilogue),
// B = x tile (N dim = x rows). 3-stage cp.async pipeline, chunks of K=64.
// ===========================================================================
__global__ void __launch_bounds__(256, 2) __cluster_dims__(1, 1, 1) w8a8_mma_silu(
    const int8_t* __restrict__ x8, const int8_t* __restrict__ w8,
    const __half* __restrict__ x16, const __half* __restrict__ w16,
    const float* __restrict__ bias, const float* __restrict__ alpha_p,
    float* __restrict__ out, int Nout)
{
#if USE_TCGEN05
    extern __shared__ uint8_t smem[];
    const int tid = threadIdx.x;
    const int wid = tid >> 5;
    const int lid = tid & 31;
    const uint32_t sbase = cvta_smem(smem);
    const uint32_t mb = sbase + 16;           // 3 mbarriers at +16,+24,+32

    if (wid == 0) {
        asm volatile("tcgen05.alloc.cta_group::1.sync.aligned.shared::cta.b32 [%0], %1;"
                     :: "r"(sbase), "r"(128u) : "memory");
        asm volatile("tcgen05.relinquish_alloc_permit.cta_group::1.sync.aligned;");
    }
    if (tid == 0) {
        #pragma unroll
        for (int s = 0; s < NSTAGE; s++)
            asm volatile("mbarrier.init.shared.b64 [%0], %1;" :: "r"(mb + 8u * s), "r"(1u) : "memory");
    }
    __syncthreads();

    uint32_t tmem;
    asm volatile("ld.shared.b32 %0, [%1];" : "=r"(tmem) : "r"(sbase));

    // Copy plan: 2048 16B segments per stage (A:1024, B:1024), thread t
    // handles idx = t + 256*j. fp16 row = 8192 B; chunk kk advances 128 B.
    const int8_t* sb[8];
    uint32_t dof[8];
    #pragma unroll
    for (int j = 0; j < 8; j++) {
        int idx  = tid + 256 * j;
        int tile = idx >> 10;            // 0 = A (weight), 1 = B (x)
        int sidx = idx & 1023;
        int row  = sidx >> 3;
        int segb = (sidx & 7) * 16;
        sb[j] = tile ? (const int8_t*)x16 + (size_t)(blockIdx.y * 128 + row) * (K_DIM * 2) + segb
                     : (const int8_t*)w16 + (size_t)(blockIdx.x * 128 + row) * (K_DIM * 2) + segb;
        uint32_t off = (uint32_t)(row * 128 + segb);
        off ^= (off >> 3) & 0x70;        // SW128 swizzle (16B granular)
        dof[j] = sbase + SM_TILES + tile * 16384 + off;
    }

#define FILL(S, KK) do {                                                   \
        uint32_t _b = (uint32_t)(S) * SM_STAGE;                            \
        _Pragma("unroll")                                                  \
        for (int j = 0; j < 8; j++) CP16(dof[j] + _b, sb[j] + (KK) * 128); \
        asm volatile("cp.async.commit_group;");                            \
    } while (0)

    FILL(0, 0);
    FILL(1, 1);

    uint32_t phv = 0;   // per-stage wait parities (bit s)
    for (int kk = 0; kk < KIT; kk++) {
        const int s = kk % 3;
        if (kk + 1 < KIT) asm volatile("cp.async.wait_group 1;");
        else              asm volatile("cp.async.wait_group 0;");
        asm volatile("fence.proxy.async.shared::cta;" ::: "memory");
        __syncthreads();

        if (wid == 0 && elect_one()) {
            uint32_t abase = sbase + SM_TILES + (uint32_t)s * SM_STAGE;
            uint64_t dA = make_desc(abase);
            uint64_t dB = make_desc(abase + 16384);
            #pragma unroll
            for (int st = 0; st < 4; st++)   // 4 x K=16 covers 64 fp16 (128 B)
                mma_f16_ss(tmem, dA + 2 * st, dB + 2 * st, (kk | st) ? 1u : 0u);
            asm volatile("tcgen05.commit.cta_group::1.mbarrier::arrive::one.shared::cluster.b64 [%0];"
                         :: "r"(mb + 8u * s) : "memory");
        }

        if (kk + 2 < KIT) {
            const int s2 = (kk + 2) % 3;
            if (kk >= 1) {                   // stage s2 last consumed by MMA(kk-1)
                mbar_wait(mb + 8u * s2, (phv >> s2) & 1u);
                phv ^= 1u << s2;
            }
            FILL(s2, kk + 2);
        }
    }
#undef FILL

    {
        const int sl = (KIT - 1) % 3;        // in-order MMAs: last commit = all done
        mbar_wait(mb + 8u * sl, (phv >> sl) & 1u);
    }
    asm volatile("tcgen05.fence::after_thread_sync;" ::: "memory");

    // Epilogue: TMEM lane = n (feature), column = m (x row). Warp w reads
    // subpartition w&3, columns [(w>>2)*64, +64).
    const float alpha = *alpha_p;
    const int cbase = (wid >> 2) * 64;
    const int n = blockIdx.x * 128 + (wid & 3) * 32 + lid;
    const float bv = bias[n];
    uint32_t r0[32], r1[32];
    ldtm_x32(r0, tmem + cbase);
    ldtm_x32(r1, tmem + cbase + 32);
    asm volatile("tcgen05.wait::ld.sync.aligned;" ::: "memory");

    float* op = out + (size_t)(blockIdx.y * 128 + cbase) * Nout + n;
    #pragma unroll
    for (int c = 0; c < 32; c++) {
        float y = fmaf(alpha, __uint_as_float(r0[c]), bv);
        op[(size_t)c * Nout] = silu(y);
    }
    #pragma unroll
    for (int c = 0; c < 32; c++) {
        float y = fmaf(alpha, __uint_as_float(r1[c]), bv);
        op[(size_t)(c + 32) * Nout] = silu(y);
    }

    __syncthreads();
    if (wid == 0)
        asm volatile("tcgen05.dealloc.cta_group::1.sync.aligned.b32 %0, %1;" :: "r"(tmem), "r"(128u));

#else  // ---------------- non-'a' pass: PROVEN R7 mma.sync int8 body ----------------
    const int8_t* x = x8;
    const int8_t* wgt = w8;
    #define BM 128
    #define BN 128
    #define BKB 32
    #define KCH (K_DIM / BKB)
    #define SROW 48
    #define STG_BYTES (BM * SROW)
    __shared__ uint8_t As[2][STG_BYTES];
    __shared__ uint8_t Bs[2][STG_BYTES];

    const int tid = threadIdx.x;
    const int l   = tid & 31;
    const int w   = tid >> 5;
    const int wm  = w >> 2;
    const int wn  = w & 3;
    const int row = tid >> 1;
    const int seg = (tid & 1) * 16;

    const int8_t* xsrc = x   + (size_t)(blockIdx.y * BM + row) * K_DIM + seg;
    const int8_t* wsrc = wgt + (size_t)(blockIdx.x * BN + row) * K_DIM + seg;

    uint32_t a_dst[2], b_dst[2];
    #pragma unroll
    for (int s = 0; s < 2; s++) {
        a_dst[s] = (uint32_t)__cvta_generic_to_shared(&As[s][row * SROW + seg]);
        b_dst[s] = (uint32_t)__cvta_generic_to_shared(&Bs[s][row * SROW + seg]);
    }
    asm volatile("cp.async.cg.shared.global [%0], [%1], 16;" :: "r"(a_dst[0]), "l"(xsrc));
    asm volatile("cp.async.cg.shared.global [%0], [%1], 16;" :: "r"(b_dst[0]), "l"(wsrc));
    asm volatile("cp.async.commit_group;");

    int acc[4][4][4];
    #pragma unroll
    for (int i = 0; i < 4; i++)
        #pragma unroll
        for (int j = 0; j < 4; j++)
            #pragma unroll
            for (int r = 0; r < 4; r++) acc[i][j][r] = 0;

    const int fr = l >> 2;
    const int fc = (l & 3) * 4;

    for (int kk = 0; kk < KCH; kk++) {
        const int cur = kk & 1;
        if (kk + 1 < KCH) {
            const int nxt = cur ^ 1;
            asm volatile("cp.async.cg.shared.global [%0], [%1], 16;"
                         :: "r"(a_dst[nxt]), "l"(xsrc + (kk + 1) * BKB));
            asm volatile("cp.async.cg.shared.global [%0], [%1], 16;"
                         :: "r"(b_dst[nxt]), "l"(wsrc + (kk + 1) * BKB));
            asm volatile("cp.async.commit_group;");
            asm volatile("cp.async.wait_group 1;");
        } else {
            asm volatile("cp.async.wait_group 0;");
        }
        __syncthreads();

        uint32_t a[4][4];
        #pragma unroll
        for (int i = 0; i < 4; i++) {
            const int r0 = (wm * 64 + i * 16 + fr) * SROW + fc;
            a[i][0] = *(const uint32_t*)&As[cur][r0];
            a[i][1] = *(const uint32_t*)&As[cur][r0 + 8 * SROW];
            a[i][2] = *(const uint32_t*)&As[cur][r0 + 16];
            a[i][3] = *(const uint32_t*)&As[cur][r0 + 8 * SROW + 16];
        }
        uint32_t b[4][2];
        #pragma unroll
        for (int j = 0; j < 4; j++) {
            const int c0 = (wn * 32 + j * 8 + fr) * SROW + fc;
            b[j][0] = *(const uint32_t*)&Bs[cur][c0];
            b[j][1] = *(const uint32_t*)&Bs[cur][c0 + 16];
        }
        #pragma unroll
        for (int i = 0; i < 4; i++)
            #pragma unroll
            for (int j = 0; j < 4; j++)
                asm volatile(
                    "mma.sync.aligned.m16n8k32.row.col.s32.s8.s8.s32 "
                    "{%0,%1,%2,%3}, {%4,%5,%6,%7}, {%8,%9}, {%0,%1,%2,%3};"
                    : "+r"(acc[i][j][0]), "+r"(acc[i][j][1]),
                      "+r"(acc[i][j][2]), "+r"(acc[i][j][3])
                    : "r"(a[i][0]), "r"(a[i][1]), "r"(a[i][2]), "r"(a[i][3]),
                      "r"(b[j][0]), "r"(b[j][1]));
        __syncthreads();
    }

    const float alpha = *alpha_p;
    #pragma unroll
    for (int i = 0; i < 4; i++) {
        #pragma unroll
        for (int h = 0; h < 2; h++) {
            const int m = blockIdx.y * BM + wm * 64 + i * 16 + fr + h * 8;
            float* orow = out + (size_t)m * Nout;
            #pragma unroll
            for (int j = 0; j < 4; j++) {
                const int n2 = blockIdx.x * BN + wn * 32 + j * 8 + (l & 3) * 2;
                const float b0 = bias[n2], b1 = bias[n2 + 1];
                float y0 = fmaf(alpha, (float)acc[i][j][h * 2],     b0);
                float y1 = fmaf(alpha, (float)acc[i][j][h * 2 + 1], b1);
                float2 v = make_float2(silu(y0), silu(y1));
                *(float2*)(orow + n2) = v;
            }
        }
    }
#endif
}

extern "C" void kernel_launch(void* const* d_in, const int* in_sizes, int n_in,
                              void* d_out, int out_size) {
    // Order-independent binding by element count (pairwise distinct)
    const void* xr = nullptr; const void* wr = nullptr;
    const float* bias = nullptr; const float* alpha = nullptr;
    long long xsz = 0, bsz = 0;

    int big0 = -1, big1 = -1;
    for (int i = 0; i < n_in; i++) {
        long long s = in_sizes[i];
        if (s == 1)            alpha = (const float*)d_in[i];
        else if (s > 100000) { if (big0 < 0) big0 = i; else big1 = i; }
        else                 { bias = (const float*)d_in[i]; bsz = s; }
    }
    long long wsz;
    if ((long long)in_sizes[big0] >= (long long)in_sizes[big1]) {
        wr = d_in[big0]; wsz = in_sizes[big0];
        xr = d_in[big1]; xsz = in_sizes[big1];
    } else {
        wr = d_in[big1]; wsz = in_sizes[big1];
        xr = d_in[big0]; xsz = in_sizes[big0];
    }

    float* out = (float*)d_out;
    const int Nout  = (int)bsz;             // 11008
    const int Mrows = (int)(xsz / K_DIM);   // 8192

    void *x8p, *w8p, *x16p, *w16p;
    cudaGetSymbolAddress(&x8p, g_x8);
    cudaGetSymbolAddress(&w8p, g_w8);
    cudaGetSymbolAddress(&x16p, g_x16);
    cudaGetSymbolAddress(&w16p, g_w16);

    // Pre-pass: canonicalize 32-bit-stored int8 tensors into int8 + fp16
    {
        int n4x = (int)(xsz / 4);
        int n4w = (int)(wsz / 4);
        cvt32<<<(n4x + 255) / 256, 256>>>((const uint32_t*)xr, (int8_t*)x8p, (__half*)x16p, n4x);
        cvt32<<<(n4w + 255) / 256, 256>>>((const uint32_t*)wr, (int8_t*)w8p, (__half*)w16p, n4w);
    }

    cudaFuncSetAttribute(w8a8_mma_silu, cudaFuncAttributeMaxDynamicSharedMemorySize, SMEM_DYN);

    // n-tiles fast: weight panel stays L2-resident across m-waves
    dim3 grid(Nout / 128, Mrows / 128);
    w8a8_mma_silu<<<grid, 256, SMEM_DYN>>>((const int8_t*)x8p, (const int8_t*)w8p,
                                           (const __half*)x16p, (const __half*)w16p,
                                           bias, alpha, out, Nout);
}